// round 14
// baseline (speedup 1.0000x reference)
#include <cuda_runtime.h>
#include <cuda_fp16.h>
#include <math.h>
#include <cstdint>

#define Bb   2
#define Nn   2048
#define Dd   1024
#define Hh   16
#define DHh  64
#define Mm   (Bb*Nn)      // 4096 rows
#define HDd  (Hh*DHh)     // 1024
#define KDIM 1024
#define LNEPS 1e-5f
#define SOFT_SCALE (0.125f * 1.44269504088896f)   // 1/sqrt(64) * log2(e)

// ---- device scratch ----
__device__ __half g_xn[(size_t)Mm*Dd];
__device__ __half g_cn[(size_t)Mm*Dd];
__device__ __half g_q [(size_t)Mm*HDd];
__device__ __half g_kv[(size_t)Mm*2*HDd];
__device__ __half g_ao[(size_t)Mm*HDd];
__device__ __half g_wTq [(size_t)HDd*Dd];
__device__ __half g_wTkv[(size_t)2*HDd*Dd];
__device__ __half g_wTo [(size_t)Dd*HDd];

__device__ __forceinline__ uint32_t smem_u32(const void* p) {
    uint32_t a;
    asm("{ .reg .u64 t; cvta.to.shared.u64 t, %1; cvt.u32.u64 %0, t; }"
        : "=r"(a) : "l"(p));
    return a;
}

#define MMA16816(d, a, b0, b1) \
    asm volatile("mma.sync.aligned.m16n8k16.row.col.f32.f16.f16.f32 " \
        "{%0,%1,%2,%3}, {%4,%5,%6,%7}, {%8,%9}, {%0,%1,%2,%3};" \
        : "+f"((d)[0]), "+f"((d)[1]), "+f"((d)[2]), "+f"((d)[3]) \
        : "r"((a)[0]), "r"((a)[1]), "r"((a)[2]), "r"((a)[3]), \
          "r"(b0), "r"(b1))

#define LDSM4(r, addr) \
    asm volatile("ldmatrix.sync.aligned.m8n8.x4.shared.b16 {%0,%1,%2,%3}, [%4];" \
        : "=r"((r)[0]), "=r"((r)[1]), "=r"((r)[2]), "=r"((r)[3]) : "r"(addr))
#define LDSM4T(r, addr) \
    asm volatile("ldmatrix.sync.aligned.m8n8.x4.trans.shared.b16 {%0,%1,%2,%3}, [%4];" \
        : "=r"((r)[0]), "=r"((r)[1]), "=r"((r)[2]), "=r"((r)[3]) : "r"(addr))
#define LDSM2T(r, addr) \
    asm volatile("ldmatrix.sync.aligned.m8n8.x2.trans.shared.b16 {%0,%1}, [%2];" \
        : "=r"((r)[0]), "=r"((r)[1]) : "r"(addr))

#define CP16(dst_u32, src_ptr) \
    asm volatile("cp.async.cg.shared.global [%0], [%1], 16;" \
        :: "r"(dst_u32), "l"(src_ptr))
#define CP_COMMIT() asm volatile("cp.async.commit_group;" ::: "memory")
#define CP_WAIT(n)  asm volatile("cp.async.wait_group %0;" :: "n"(n) : "memory")

#define HEX2(d, s) \
    asm volatile("ex2.approx.f16x2 %0, %1;" : "=r"(d) : "r"(s))

#define STCS2(ptr, a, b) \
    asm volatile("st.global.cs.v2.f32 [%0], {%1, %2};" \
        :: "l"(ptr), "f"(a), "f"(b) : "memory")

__device__ __forceinline__ uint32_t pack_h2(float a, float b) {
    __half2 h = __floats2half2_rn(a, b);
    return *(uint32_t*)&h;
}

// ============================================================
// Merged prolog: LayerNorm rows (blocks 0..4095) +
// weight transposes (blocks 4096..8191). One launch.
// ============================================================
__global__ __launch_bounds__(256) void prep_kernel(
    const float* __restrict__ x,
    const float* __restrict__ g1, const float* __restrict__ b1,
    const float* __restrict__ g2, const float* __restrict__ b2,
    const float* __restrict__ Wq, const float* __restrict__ Wkv,
    const float* __restrict__ Wo)
{
    const int bid = blockIdx.x;
    const int t = threadIdx.x;

    if (bid < Mm) {
        const int row = bid;
        const float* xr = x + (size_t)row * Dd;
        float v[4]; float s = 0.f, ss = 0.f;
#pragma unroll
        for (int i = 0; i < 4; i++) {
            float val = xr[t + i*256];
            v[i] = val; s += val; ss += val*val;
        }
#pragma unroll
        for (int o = 16; o > 0; o >>= 1) {
            s  += __shfl_xor_sync(0xffffffffu, s,  o);
            ss += __shfl_xor_sync(0xffffffffu, ss, o);
        }
        __shared__ float rs[8], rss[8];
        const int w = t >> 5, l = t & 31;
        if (l == 0) { rs[w] = s; rss[w] = ss; }
        __syncthreads();
        if (t == 0) {
            float a = 0.f, c = 0.f;
            for (int i = 0; i < 8; i++) { a += rs[i]; c += rss[i]; }
            rs[0] = a; rss[0] = c;
        }
        __syncthreads();
        const float mean = rs[0] * (1.f/Dd);
        const float var  = rss[0] * (1.f/Dd) - mean*mean;
        const float rstd = rsqrtf(var + LNEPS);

        __half* xn = g_xn + (size_t)row*Dd;
        __half* cn = g_cn + (size_t)row*Dd;
#pragma unroll
        for (int i = 0; i < 4; i++) {
            int idx = t + i*256;
            float nv = (v[i] - mean) * rstd;
            xn[idx] = __float2half_rn(nv * g1[idx] + b1[idx]);
            cn[idx] = __float2half_rn(nv * g2[idx] + b2[idx]);
        }
    } else {
        int idx = bid - Mm;
        const float* W; __half* WT; int K, Nc;
        if (idx < 1024)       { W = Wq;  K = Dd;  Nc = HDd;   WT = g_wTq; }
        else if (idx < 3072)  { W = Wkv; K = Dd;  Nc = 2*HDd; WT = g_wTkv; idx -= 1024; }
        else                  { W = Wo;  K = HDd; Nc = Dd;    WT = g_wTo;  idx -= 3072; }
        const int nb = Nc / 32;
        const int bn = (idx % nb) * 32, bk = (idx / nb) * 32;

        __shared__ float tile[32][33];
        const int x2 = t & 31, y2 = t >> 5;
#pragma unroll
        for (int i = 0; i < 32; i += 8)
            tile[y2 + i][x2] = W[(size_t)(bk + y2 + i) * Nc + bn + x2];
        __syncthreads();
#pragma unroll
        for (int i = 0; i < 32; i += 8)
            WT[(size_t)(bn + y2 + i) * K + bk + x2] = __float2half_rn(tile[x2][y2 + i]);
    }
}

// ============================================================
// fp16 HMMA GEMM (qkv, proven R7 config): CTA 128x128,
// 4 warps (2x2), warp 64x64, K-chunk 32, 3-stage cp.async.
// ============================================================
#define CHUNKB 10240
#define NSTAGE 3
#define GSMEM (NSTAGE*2*CHUNKB)   // 61440

__device__ __forceinline__ void gemm_body128(
    const __half* __restrict__ Ah, const __half* __restrict__ BTh,
    __half* __restrict__ C, int Nc, int row0, int col0, float oscale)
{
    extern __shared__ char gsm[];
    const uint32_t asb = smem_u32(gsm);
    const uint32_t bsb = asb + NSTAGE*CHUNKB;

    const int t = threadIdx.x;
    const int lane = t & 31, wid = t >> 5;
    const int wm = wid >> 1, wn = wid & 1;
    const int r0 = t >> 2, c8 = t & 3;
    const __half* Ap = Ah  + (size_t)(row0 + r0) * KDIM + c8 * 8;
    const __half* Bp = BTh + (size_t)(col0 + r0) * KDIM + c8 * 8;
    const uint32_t st_off = (uint32_t)(r0 * 80 + c8 * 16);

    const uint32_t a_l_off = (uint32_t)((wm*64 + (lane & 7) + ((lane >> 3) & 1) * 8) * 80
                                        + ((lane >> 4) & 1) * 16);
    const uint32_t b_l_off = (uint32_t)((wn*64 + (lane & 7) + ((lane >> 4) & 1) * 8) * 80
                                        + ((lane >> 3) & 1) * 16);

    float c[4][8][4];
#pragma unroll
    for (int i = 0; i < 4; i++)
#pragma unroll
        for (int j = 0; j < 8; j++)
#pragma unroll
            for (int q = 0; q < 4; q++) c[i][j][q] = 0.f;

#pragma unroll
    for (int st = 0; st < 2; st++) {
#pragma unroll
        for (int i = 0; i < 4; i++) {
            CP16(asb + st*CHUNKB + st_off + i*(32*80), Ap + st*32 + (size_t)(32*i)*KDIM);
            CP16(bsb + st*CHUNKB + st_off + i*(32*80), Bp + st*32 + (size_t)(32*i)*KDIM);
        }
        CP_COMMIT();
    }

    for (int ch = 0; ch < 32; ch++) {
        CP_WAIT(1);
        __syncthreads();

        if (ch + 2 < 32) {
            const int st = (ch + 2) % 3;
#pragma unroll
            for (int i = 0; i < 4; i++) {
                CP16(asb + st*CHUNKB + st_off + i*(32*80), Ap + (ch+2)*32 + (size_t)(32*i)*KDIM);
                CP16(bsb + st*CHUNKB + st_off + i*(32*80), Bp + (ch+2)*32 + (size_t)(32*i)*KDIM);
            }
        }
        CP_COMMIT();

        const int cs = ch % 3;
        const uint32_t ab = asb + cs*CHUNKB + a_l_off;
        const uint32_t bb = bsb + cs*CHUNKB + b_l_off;
#pragma unroll
        for (int ks = 0; ks < 2; ks++) {
            uint32_t a[4][4], b[4][4];
#pragma unroll
            for (int im = 0; im < 4; im++)
                LDSM4(a[im], ab + im * (16*80) + ks * 32);
#pragma unroll
            for (int jq = 0; jq < 4; jq++)
                LDSM4(b[jq], bb + jq * (16*80) + ks * 32);
#pragma unroll
            for (int im = 0; im < 4; im++)
#pragma unroll
                for (int jq = 0; jq < 4; jq++) {
                    MMA16816(c[im][2*jq],   a[im], b[jq][0], b[jq][1]);
                    MMA16816(c[im][2*jq+1], a[im], b[jq][2], b[jq][3]);
                }
        }
    }

    const int g  = lane >> 2;
    const int tq = lane & 3;
#pragma unroll
    for (int im = 0; im < 4; im++) {
#pragma unroll
        for (int jn = 0; jn < 8; jn++) {
            const int row = row0 + wm*64 + im*16 + g;
            const int col = col0 + wn*64 + jn*8 + tq*2;
            *(uint32_t*)(C + (size_t)row * Nc + col) =
                pack_h2(c[im][jn][0]*oscale, c[im][jn][1]*oscale);
            *(uint32_t*)(C + (size_t)(row + 8) * Nc + col) =
                pack_h2(c[im][jn][2]*oscale, c[im][jn][3]*oscale);
        }
    }
}

__global__ __launch_bounds__(128) void gemm_qkv()
{
    const int bx = blockIdx.x;
    const int row0 = blockIdx.y * 128;
    if (bx < 8)
        gemm_body128(g_xn, g_wTq,  g_q,  HDd,   row0, bx * 128, SOFT_SCALE);
    else
        gemm_body128(g_cn, g_wTkv, g_kv, 2*HDd, row0, (bx - 8) * 128, 1.0f);
}

// ============================================================
// O projection (measured-best R10 config): CTA 128x128,
// 4 warps (2x2), warp 64x64, 3-stage, grid (8, 32) = 256 CTAs.
// fp32 output via streaming stores (write-once, never re-read).
// ============================================================
__global__ __launch_bounds__(128) void gemm_o(float* __restrict__ out)
{
    extern __shared__ char gsm[];
    const uint32_t asb = smem_u32(gsm);
    const uint32_t bsb = asb + NSTAGE*CHUNKB;

    const int t = threadIdx.x;
    const int lane = t & 31, wid = t >> 5;
    const int wm = wid >> 1, wn = wid & 1;
    const int row0 = blockIdx.y * 128, col0 = blockIdx.x * 128;

    const int r0 = t >> 2, c8 = t & 3;
    const __half* Ap = g_ao  + (size_t)(row0 + r0) * KDIM + c8 * 8;
    const __half* Bp = g_wTo + (size_t)(col0 + r0) * KDIM + c8 * 8;
    const uint32_t st_off = (uint32_t)(r0 * 80 + c8 * 16);

    const uint32_t a_l_off = (uint32_t)((wm*64 + (lane & 7) + ((lane >> 3) & 1) * 8) * 80
                                        + ((lane >> 4) & 1) * 16);
    const uint32_t b_l_off = (uint32_t)((wn*64 + (lane & 7) + ((lane >> 4) & 1) * 8) * 80
                                        + ((lane >> 3) & 1) * 16);

    float c[4][8][4];
#pragma unroll
    for (int i = 0; i < 4; i++)
#pragma unroll
        for (int j = 0; j < 8; j++)
#pragma unroll
            for (int q = 0; q < 4; q++) c[i][j][q] = 0.f;

#pragma unroll
    for (int st = 0; st < 2; st++) {
#pragma unroll
        for (int i = 0; i < 4; i++) {
            CP16(asb + st*CHUNKB + st_off + i*(32*80), Ap + st*32 + (size_t)(32*i)*KDIM);
            CP16(bsb + st*CHUNKB + st_off + i*(32*80), Bp + st*32 + (size_t)(32*i)*KDIM);
        }
        CP_COMMIT();
    }

    for (int ch = 0; ch < 32; ch++) {
        CP_WAIT(1);
        __syncthreads();

        if (ch + 2 < 32) {
            const int st = (ch + 2) % 3;
#pragma unroll
            for (int i = 0; i < 4; i++) {
                CP16(asb + st*CHUNKB + st_off + i*(32*80), Ap + (ch+2)*32 + (size_t)(32*i)*KDIM);
                CP16(bsb + st*CHUNKB + st_off + i*(32*80), Bp + (ch+2)*32 + (size_t)(32*i)*KDIM);
            }
        }
        CP_COMMIT();

        const int cs = ch % 3;
        const uint32_t ab = asb + cs*CHUNKB + a_l_off;
        const uint32_t bb = bsb + cs*CHUNKB + b_l_off;
#pragma unroll
        for (int ks = 0; ks < 2; ks++) {
            uint32_t a[4][4], b[4][4];
#pragma unroll
            for (int im = 0; im < 4; im++)
                LDSM4(a[im], ab + im * (16*80) + ks * 32);
#pragma unroll
            for (int jq = 0; jq < 4; jq++)
                LDSM4(b[jq], bb + jq * (16*80) + ks * 32);
#pragma unroll
            for (int im = 0; im < 4; im++)
#pragma unroll
                for (int jq = 0; jq < 4; jq++) {
                    MMA16816(c[im][2*jq],   a[im], b[jq][0], b[jq][1]);
                    MMA16816(c[im][2*jq+1], a[im], b[jq][2], b[jq][3]);
                }
        }
    }

    const int g  = lane >> 2;
    const int tq = lane & 3;
#pragma unroll
    for (int im = 0; im < 4; im++) {
#pragma unroll
        for (int jn = 0; jn < 8; jn++) {
            const int row = row0 + wm*64 + im*16 + g;
            const int col = col0 + wn*64 + jn*8 + tq*2;
            STCS2(out + (size_t)row * Dd + col,       c[im][jn][0], c[im][jn][1]);
            STCS2(out + (size_t)(row + 8) * Dd + col, c[im][jn][2], c[im][jn][3]);
        }
    }
}

// ============================================================
// HMMA causal flash attention — 128 threads, 4 warps,
// 32 Q rows/warp (two 16-row blocks). S computed ONE TILE AHEAD
// (sa registers reused: dead after pf is built), so softmax never
// waits on just-issued MMAs. BQ=128, BK=64, 3-buffer cp.async
// ring, longest-first, lsum via ones-column MMA, fp16 ex2.
// ============================================================
#define BQ 128
#define BK 64
#define KPAD 72
#define KPADB 144
#define QS_H  (BQ*KPAD)
#define KVT_H (BK*KPAD)
#define FSM2 ((QS_H + 6*KVT_H) * 2)   // 73728

__global__ __launch_bounds__(128) void flash_hmma(
    const __half* __restrict__ q, const __half* __restrict__ kv,
    __half* __restrict__ o)
{
    extern __shared__ __half sh[];
    __half* Qs  = sh;
    __half* Vsp = sh + QS_H + 3*KVT_H;

    const int t = threadIdx.x, lane = t & 31, w = t >> 5;
    const int bq = gridDim.x - 1 - blockIdx.x;   // longest-first
    const int bh = blockIdx.y;
    const int b = bh >> 4, h = bh & 15;
    const int row0 = bq * BQ;

    const uint32_t shb = smem_u32(sh);
    const uint32_t ksb = shb + QS_H*2;
    const uint32_t vsb = ksb + 3*KVT_H*2;

#pragma unroll
    for (int i = 0; i < 8; i++) {
        int e = t + i * 128;
        int r = e >> 3, qq = e & 7;
        *(uint4*)(Qs + r * KPAD + qq * 8) =
            *(const uint4*)(q + (size_t)(b*Nn + row0 + r) * HDd + h * DHh + qq * 8);
    }
    for (int i = t; i < 192; i += 128) {
        const int buf = i >> 6, r = i & 63;
        uint4 ones = make_uint4(0x00003C00u, 0u, 0u, 0u);
        *(uint4*)(Vsp + buf * KVT_H + r * KPAD + 64) = ones;
    }

    const __half* kvbase = kv + (size_t)(b*Nn) * (2*HDd) + h * DHh;
    const int jt_max = row0 / BK + 1;

    const int lr = t >> 3, lq = t & 7;
    auto issue_kv = [&](int jt, int buf) {
        const uint32_t kd = ksb + (uint32_t)buf * (KVT_H*2);
        const uint32_t vd = vsb + (uint32_t)buf * (KVT_H*2);
#pragma unroll
        for (int rr = 0; rr < 64; rr += 16) {
            const __half* p = kvbase + (size_t)(jt*BK + lr + rr) * (2*HDd) + lq * 8;
            CP16(kd + (lr+rr)*KPADB + lq*16, p);
            CP16(vd + (lr+rr)*KPADB + lq*16, p + HDd);
        }
    };

    issue_kv(0, 0); CP_COMMIT();
    issue_kv(1, 1); CP_COMMIT();

    __syncthreads();   // Q + V-pad visible

    uint32_t qf[2][4][4];
#pragma unroll
    for (int blk = 0; blk < 2; blk++) {
        const uint32_t qb = shb
            + (uint32_t)((w*32 + blk*16 + (lane & 7) + ((lane >> 3) & 1) * 8) * KPADB
                         + ((lane >> 4) & 1) * 16);
#pragma unroll
        for (int ks = 0; ks < 4; ks++)
            LDSM4(qf[blk][ks], qb + ks * 32);
    }

    const uint32_t k_off = (uint32_t)(((lane & 7) + ((lane >> 3) & 1) * 8) * KPADB
                                      + ((lane >> 4) & 1) * 16);
    const uint32_t v1_off = (uint32_t)(((lane & 7) + ((lane >> 3) & 1) * 8) * KPADB + 128);

    float m_prev[2][2] = {{-1e30f, -1e30f}, {-1e30f, -1e30f}};
    float oa[2][8][4];
    float oae[2][4];
#pragma unroll
    for (int blk = 0; blk < 2; blk++) {
#pragma unroll
        for (int jn = 0; jn < 8; jn++)
#pragma unroll
            for (int cc = 0; cc < 4; cc++) oa[blk][jn][cc] = 0.f;
#pragma unroll
        for (int cc = 0; cc < 4; cc++) oae[blk][cc] = 0.f;
    }

    const int wrow = row0 + w*32;
    const int lrow = wrow + (lane >> 2);

    float sa[2][8][4];   // S tile accumulator (reused across pipeline stages)

    // computeS: zero sa, S-MMAs on K buf, apply causal mask for tile jt.
    auto computeS = [&](int jt) {
        const int buf = jt % 3;
#pragma unroll
        for (int blk = 0; blk < 2; blk++)
#pragma unroll
            for (int jn = 0; jn < 8; jn++)
#pragma unroll
                for (int cc = 0; cc < 4; cc++) sa[blk][jn][cc] = 0.f;

        const uint32_t kb = ksb + (uint32_t)buf * (KVT_H*2) + k_off;
#pragma unroll
        for (int ks = 0; ks < 4; ks++) {
#pragma unroll
            for (int jp = 0; jp < 4; jp++) {
                uint32_t kr[4];
                LDSM4(kr, kb + jp * (16*KPADB) + ks * 32);
                MMA16816(sa[0][2*jp],   qf[0][ks], kr[0], kr[2]);
                MMA16816(sa[0][2*jp+1], qf[0][ks], kr[1], kr[3]);
                MMA16816(sa[1][2*jp],   qf[1][ks], kr[0], kr[2]);
                MMA16816(sa[1][2*jp+1], qf[1][ks], kr[1], kr[3]);
            }
        }

        const bool diag = (jt*BK + BK - 1 > wrow);
        if (diag) {
#pragma unroll
            for (int blk = 0; blk < 2; blk++)
#pragma unroll
                for (int jn = 0; jn < 8; jn++)
#pragma unroll
                    for (int cc = 0; cc < 4; cc++) {
                        int col = jt*BK + jn*8 + (lane & 3)*2 + (cc & 1);
                        int row = lrow + blk*16 + (cc >> 1)*8;
                        if (col > row) sa[blk][jn][cc] = -1e30f;
                    }
        }
    };

    // prologue: tile 0's S computed ahead of the loop
    CP_WAIT(1);        // G0 (tile 0) complete
    __syncthreads();   // visible to all warps
    computeS(0);       // tile 0 never fully masked for any warp

    for (int jt = 0; jt <= jt_max; jt++) {
        const bool fm_cur = (jt*BK > wrow + 31);

        // ---- phase A: softmax on sa (tile jt) -> pf; rescale ----
        uint32_t pf[2][4][4];
        if (!fm_cur) {
            float mnew[2][2], alpha[2][2];
#pragma unroll
            for (int blk = 0; blk < 2; blk++) {
                float rmax[2] = {-1e30f, -1e30f};
#pragma unroll
                for (int jn = 0; jn < 8; jn++) {
                    rmax[0] = fmaxf(rmax[0], fmaxf(sa[blk][jn][0], sa[blk][jn][1]));
                    rmax[1] = fmaxf(rmax[1], fmaxf(sa[blk][jn][2], sa[blk][jn][3]));
                }
#pragma unroll
                for (int k2 = 0; k2 < 2; k2++) {
                    rmax[k2] = fmaxf(rmax[k2], __shfl_xor_sync(0xffffffffu, rmax[k2], 1));
                    rmax[k2] = fmaxf(rmax[k2], __shfl_xor_sync(0xffffffffu, rmax[k2], 2));
                    mnew[blk][k2]  = fmaxf(m_prev[blk][k2], rmax[k2]);
                    alpha[blk][k2] = exp2f(m_prev[blk][k2] - mnew[blk][k2]);
                    m_prev[blk][k2] = mnew[blk][k2];
                }
            }
#pragma unroll
            for (int blk = 0; blk < 2; blk++) {
#pragma unroll
                for (int jn = 0; jn < 8; jn++)
#pragma unroll
                    for (int cc = 0; cc < 4; cc++)
                        oa[blk][jn][cc] *= alpha[blk][cc >> 1];
#pragma unroll
                for (int cc = 0; cc < 4; cc++)
                    oae[blk][cc] *= alpha[blk][cc >> 1];
            }
#pragma unroll
            for (int blk = 0; blk < 2; blk++)
#pragma unroll
                for (int ks = 0; ks < 4; ks++) {
                    uint32_t u0 = pack_h2(sa[blk][2*ks][0]   - mnew[blk][0], sa[blk][2*ks][1]   - mnew[blk][0]);
                    uint32_t u1 = pack_h2(sa[blk][2*ks][2]   - mnew[blk][1], sa[blk][2*ks][3]   - mnew[blk][1]);
                    uint32_t u2 = pack_h2(sa[blk][2*ks+1][0] - mnew[blk][0], sa[blk][2*ks+1][1] - mnew[blk][0]);
                    uint32_t u3 = pack_h2(sa[blk][2*ks+1][2] - mnew[blk][1], sa[blk][2*ks+1][3] - mnew[blk][1]);
                    HEX2(pf[blk][ks][0], u0);
                    HEX2(pf[blk][ks][1], u1);
                    HEX2(pf[blk][ks][2], u2);
                    HEX2(pf[blk][ks][3], u3);
                }
        }

        // ---- phase B: sync, prefetch jt+2, compute S(jt+1) into sa ----
        CP_WAIT(0);
        __syncthreads();
        if (jt + 2 <= jt_max) { issue_kv(jt + 2, (jt + 2) % 3); CP_COMMIT(); }

        if (jt < jt_max) {
            const bool fm_next = ((jt+1)*BK > wrow + 31);
            if (!fm_next) computeS(jt + 1);
        }

        // ---- phase C: PV for tile jt ----
        if (!fm_cur) {
            const int buf = jt % 3;
            const uint32_t vb  = vsb + (uint32_t)buf * (KVT_H*2) + k_off;
            const uint32_t vb1 = vsb + (uint32_t)buf * (KVT_H*2) + v1_off;
#pragma unroll
            for (int ks = 0; ks < 4; ks++) {
#pragma unroll
                for (int nb = 0; nb < 4; nb++) {
                    uint32_t vr[4];
                    LDSM4T(vr, vb + ks * (16*KPADB) + nb * 32);
                    MMA16816(oa[0][2*nb],   pf[0][ks], vr[0], vr[1]);
                    MMA16816(oa[0][2*nb+1], pf[0][ks], vr[2], vr[3]);
                    MMA16816(oa[1][2*nb],   pf[1][ks], vr[0], vr[1]);
                    MMA16816(oa[1][2*nb+1], pf[1][ks], vr[2], vr[3]);
                }
                uint32_t v1[2];
                LDSM2T(v1, vb1 + ks * (16*KPADB));
                MMA16816(oae[0], pf[0][ks], v1[0], v1[1]);
                MMA16816(oae[1], pf[1][ks], v1[0], v1[1]);
            }
        }
    }

#pragma unroll
    for (int blk = 0; blk < 2; blk++) {
        float l0 = __shfl_sync(0xffffffffu, oae[blk][0], lane & ~3);
        float l1 = __shfl_sync(0xffffffffu, oae[blk][2], lane & ~3);
        float inv0 = 1.f / l0, inv1 = 1.f / l1;
        __half* ob = o + (size_t)(b*Nn + lrow + blk*16) * HDd + h * DHh + (lane & 3) * 2;
#pragma unroll
        for (int jn = 0; jn < 8; jn++) {
            *(uint32_t*)(ob + jn*8)         = pack_h2(oa[blk][jn][0]*inv0, oa[blk][jn][1]*inv0);
            *(uint32_t*)(ob + 8*HDd + jn*8) = pack_h2(oa[blk][jn][2]*inv1, oa[blk][jn][3]*inv1);
        }
    }
}

// ============================================================
// launch
// ============================================================
extern "C" void kernel_launch(void* const* d_in, const int* in_sizes, int n_in,
                              void* d_out, int out_size)
{
    const float* x     = (const float*)d_in[0];
    const float* ln_g  = (const float*)d_in[1];
    const float* ln_b  = (const float*)d_in[2];
    const float* lnc_g = (const float*)d_in[3];
    const float* lnc_b = (const float*)d_in[4];
    const float* Wq    = (const float*)d_in[5];
    const float* Wkv   = (const float*)d_in[6];
    const float* Wo    = (const float*)d_in[7];
    float* out = (float*)d_out;

    __half *qp, *kvp, *aop;
    cudaGetSymbolAddress((void**)&qp,  g_q);
    cudaGetSymbolAddress((void**)&kvp, g_kv);
    cudaGetSymbolAddress((void**)&aop, g_ao);

    cudaFuncSetAttribute(flash_hmma,
                         cudaFuncAttributeMaxDynamicSharedMemorySize, FSM2);
    cudaFuncSetAttribute(gemm_qkv,
                         cudaFuncAttributeMaxDynamicSharedMemorySize, GSMEM);
    cudaFuncSetAttribute(gemm_o,
                         cudaFuncAttributeMaxDynamicSharedMemorySize, GSMEM);

    // 1) merged layernorm + weight transposes
    prep_kernel<<<Mm + 4096, 256>>>(x, ln_g, ln_b, lnc_g, lnc_b, Wq, Wkv, Wo);
    // 2) fused q (pre-scaled) + kv projections
    gemm_qkv<<<dim3(24, Mm/128), 128, GSMEM>>>();
    // 3) HMMA causal flash attention (S one tile ahead)
    flash_hmma<<<dim3(Nn/BQ, Bb*Hh), 128, FSM2>>>(qp, kvp, aop);
    // 4) out = ao @ Wo (128x128 tiles, streaming stores)
    gemm_o<<<dim3(Dd/128, Mm/128), 128, GSMEM>>>(out);
}

// round 15
// speedup vs baseline: 1.0267x; 1.0267x over previous
#include <cuda_runtime.h>
#include <cuda_fp16.h>
#include <math.h>
#include <cstdint>

#define Bb   2
#define Nn   2048
#define Dd   1024
#define Hh   16
#define DHh  64
#define Mm   (Bb*Nn)      // 4096 rows
#define HDd  (Hh*DHh)     // 1024
#define KDIM 1024
#define LNEPS 1e-5f
#define SOFT_SCALE (0.125f * 1.44269504088896f)   // 1/sqrt(64) * log2(e)

// ---- device scratch ----
__device__ __half g_xn[(size_t)Mm*Dd];
__device__ __half g_cn[(size_t)Mm*Dd];
__device__ __half g_q [(size_t)Mm*HDd];
__device__ __half g_kv[(size_t)Mm*2*HDd];
__device__ __half g_ao[(size_t)Mm*HDd];
__device__ __half g_wTq [(size_t)HDd*Dd];
__device__ __half g_wTkv[(size_t)2*HDd*Dd];
__device__ __half g_wTo [(size_t)Dd*HDd];

__device__ __forceinline__ uint32_t smem_u32(const void* p) {
    uint32_t a;
    asm("{ .reg .u64 t; cvta.to.shared.u64 t, %1; cvt.u32.u64 %0, t; }"
        : "=r"(a) : "l"(p));
    return a;
}

#define MMA16816(d, a, b0, b1) \
    asm volatile("mma.sync.aligned.m16n8k16.row.col.f32.f16.f16.f32 " \
        "{%0,%1,%2,%3}, {%4,%5,%6,%7}, {%8,%9}, {%0,%1,%2,%3};" \
        : "+f"((d)[0]), "+f"((d)[1]), "+f"((d)[2]), "+f"((d)[3]) \
        : "r"((a)[0]), "r"((a)[1]), "r"((a)[2]), "r"((a)[3]), \
          "r"(b0), "r"(b1))

#define LDSM4(r, addr) \
    asm volatile("ldmatrix.sync.aligned.m8n8.x4.shared.b16 {%0,%1,%2,%3}, [%4];" \
        : "=r"((r)[0]), "=r"((r)[1]), "=r"((r)[2]), "=r"((r)[3]) : "r"(addr))
#define LDSM4T(r, addr) \
    asm volatile("ldmatrix.sync.aligned.m8n8.x4.trans.shared.b16 {%0,%1,%2,%3}, [%4];" \
        : "=r"((r)[0]), "=r"((r)[1]), "=r"((r)[2]), "=r"((r)[3]) : "r"(addr))
#define LDSM2T(r, addr) \
    asm volatile("ldmatrix.sync.aligned.m8n8.x2.trans.shared.b16 {%0,%1}, [%2];" \
        : "=r"((r)[0]), "=r"((r)[1]) : "r"(addr))

#define CP16(dst_u32, src_ptr) \
    asm volatile("cp.async.cg.shared.global [%0], [%1], 16;" \
        :: "r"(dst_u32), "l"(src_ptr))
#define CP_COMMIT() asm volatile("cp.async.commit_group;" ::: "memory")
#define CP_WAIT(n)  asm volatile("cp.async.wait_group %0;" :: "n"(n) : "memory")

#define HEX2(d, s) \
    asm volatile("ex2.approx.f16x2 %0, %1;" : "=r"(d) : "r"(s))

#define STCS2(ptr, a, b) \
    asm volatile("st.global.cs.v2.f32 [%0], {%1, %2};" \
        :: "l"(ptr), "f"(a), "f"(b) : "memory")

__device__ __forceinline__ uint32_t pack_h2(float a, float b) {
    __half2 h = __floats2half2_rn(a, b);
    return *(uint32_t*)&h;
}

// ============================================================
// Merged prolog: LayerNorm rows (blocks 0..4095, vectorized) +
// weight transposes (blocks 4096..8191). One launch.
// ============================================================
__global__ __launch_bounds__(256) void prep_kernel(
    const float* __restrict__ x,
    const float* __restrict__ g1, const float* __restrict__ b1,
    const float* __restrict__ g2, const float* __restrict__ b2,
    const float* __restrict__ Wq, const float* __restrict__ Wkv,
    const float* __restrict__ Wo)
{
    const int bid = blockIdx.x;
    const int t = threadIdx.x;

    if (bid < Mm) {
        // ---- LayerNorm: 256 threads x 4 contiguous elements ----
        const int row = bid;
        const float4 xv = *(const float4*)(x + (size_t)row * Dd + t * 4);
        float s  = xv.x + xv.y + xv.z + xv.w;
        float ss = xv.x*xv.x + xv.y*xv.y + xv.z*xv.z + xv.w*xv.w;
#pragma unroll
        for (int o = 16; o > 0; o >>= 1) {
            s  += __shfl_xor_sync(0xffffffffu, s,  o);
            ss += __shfl_xor_sync(0xffffffffu, ss, o);
        }
        __shared__ float rs[8], rss[8];
        const int w = t >> 5, l = t & 31;
        if (l == 0) { rs[w] = s; rss[w] = ss; }
        __syncthreads();
        if (t == 0) {
            float a = 0.f, c = 0.f;
            for (int i = 0; i < 8; i++) { a += rs[i]; c += rss[i]; }
            rs[0] = a; rss[0] = c;
        }
        __syncthreads();
        const float mean = rs[0] * (1.f/Dd);
        const float var  = rss[0] * (1.f/Dd) - mean*mean;
        const float rstd = rsqrtf(var + LNEPS);

        const float4 gv1 = *(const float4*)(g1 + t * 4);
        const float4 bv1 = *(const float4*)(b1 + t * 4);
        const float4 gv2 = *(const float4*)(g2 + t * 4);
        const float4 bv2 = *(const float4*)(b2 + t * 4);

        float n0 = (xv.x - mean) * rstd;
        float n1 = (xv.y - mean) * rstd;
        float n2 = (xv.z - mean) * rstd;
        float n3 = (xv.w - mean) * rstd;

        uint2 o1, o2;
        o1.x = pack_h2(n0 * gv1.x + bv1.x, n1 * gv1.y + bv1.y);
        o1.y = pack_h2(n2 * gv1.z + bv1.z, n3 * gv1.w + bv1.w);
        o2.x = pack_h2(n0 * gv2.x + bv2.x, n1 * gv2.y + bv2.y);
        o2.y = pack_h2(n2 * gv2.z + bv2.z, n3 * gv2.w + bv2.w);
        *(uint2*)(g_xn + (size_t)row * Dd + t * 4) = o1;
        *(uint2*)(g_cn + (size_t)row * Dd + t * 4) = o2;
    } else {
        int idx = bid - Mm;
        const float* W; __half* WT; int K, Nc;
        if (idx < 1024)       { W = Wq;  K = Dd;  Nc = HDd;   WT = g_wTq; }
        else if (idx < 3072)  { W = Wkv; K = Dd;  Nc = 2*HDd; WT = g_wTkv; idx -= 1024; }
        else                  { W = Wo;  K = HDd; Nc = Dd;    WT = g_wTo;  idx -= 3072; }
        const int nb = Nc / 32;
        const int bn = (idx % nb) * 32, bk = (idx / nb) * 32;

        __shared__ float tile[32][33];
        const int x2 = t & 31, y2 = t >> 5;
#pragma unroll
        for (int i = 0; i < 32; i += 8)
            tile[y2 + i][x2] = W[(size_t)(bk + y2 + i) * Nc + bn + x2];
        __syncthreads();
#pragma unroll
        for (int i = 0; i < 32; i += 8)
            WT[(size_t)(bn + y2 + i) * K + bk + x2] = __float2half_rn(tile[x2][y2 + i]);
    }
}

// ============================================================
// fp16 HMMA GEMM (qkv, proven R7 config): CTA 128x128,
// 4 warps (2x2), warp 64x64, K-chunk 32, 3-stage cp.async.
// ============================================================
#define CHUNKB 10240
#define NSTAGE 3
#define GSMEM (NSTAGE*2*CHUNKB)   // 61440

__device__ __forceinline__ void gemm_body128(
    const __half* __restrict__ Ah, const __half* __restrict__ BTh,
    __half* __restrict__ C, int Nc, int row0, int col0, float oscale)
{
    extern __shared__ char gsm[];
    const uint32_t asb = smem_u32(gsm);
    const uint32_t bsb = asb + NSTAGE*CHUNKB;

    const int t = threadIdx.x;
    const int lane = t & 31, wid = t >> 5;
    const int wm = wid >> 1, wn = wid & 1;
    const int r0 = t >> 2, c8 = t & 3;
    const __half* Ap = Ah  + (size_t)(row0 + r0) * KDIM + c8 * 8;
    const __half* Bp = BTh + (size_t)(col0 + r0) * KDIM + c8 * 8;
    const uint32_t st_off = (uint32_t)(r0 * 80 + c8 * 16);

    const uint32_t a_l_off = (uint32_t)((wm*64 + (lane & 7) + ((lane >> 3) & 1) * 8) * 80
                                        + ((lane >> 4) & 1) * 16);
    const uint32_t b_l_off = (uint32_t)((wn*64 + (lane & 7) + ((lane >> 4) & 1) * 8) * 80
                                        + ((lane >> 3) & 1) * 16);

    float c[4][8][4];
#pragma unroll
    for (int i = 0; i < 4; i++)
#pragma unroll
        for (int j = 0; j < 8; j++)
#pragma unroll
            for (int q = 0; q < 4; q++) c[i][j][q] = 0.f;

#pragma unroll
    for (int st = 0; st < 2; st++) {
#pragma unroll
        for (int i = 0; i < 4; i++) {
            CP16(asb + st*CHUNKB + st_off + i*(32*80), Ap + st*32 + (size_t)(32*i)*KDIM);
            CP16(bsb + st*CHUNKB + st_off + i*(32*80), Bp + st*32 + (size_t)(32*i)*KDIM);
        }
        CP_COMMIT();
    }

    for (int ch = 0; ch < 32; ch++) {
        CP_WAIT(1);
        __syncthreads();

        if (ch + 2 < 32) {
            const int st = (ch + 2) % 3;
#pragma unroll
            for (int i = 0; i < 4; i++) {
                CP16(asb + st*CHUNKB + st_off + i*(32*80), Ap + (ch+2)*32 + (size_t)(32*i)*KDIM);
                CP16(bsb + st*CHUNKB + st_off + i*(32*80), Bp + (ch+2)*32 + (size_t)(32*i)*KDIM);
            }
        }
        CP_COMMIT();

        const int cs = ch % 3;
        const uint32_t ab = asb + cs*CHUNKB + a_l_off;
        const uint32_t bb = bsb + cs*CHUNKB + b_l_off;
#pragma unroll
        for (int ks = 0; ks < 2; ks++) {
            uint32_t a[4][4], b[4][4];
#pragma unroll
            for (int im = 0; im < 4; im++)
                LDSM4(a[im], ab + im * (16*80) + ks * 32);
#pragma unroll
            for (int jq = 0; jq < 4; jq++)
                LDSM4(b[jq], bb + jq * (16*80) + ks * 32);
#pragma unroll
            for (int im = 0; im < 4; im++)
#pragma unroll
                for (int jq = 0; jq < 4; jq++) {
                    MMA16816(c[im][2*jq],   a[im], b[jq][0], b[jq][1]);
                    MMA16816(c[im][2*jq+1], a[im], b[jq][2], b[jq][3]);
                }
        }
    }

    const int g  = lane >> 2;
    const int tq = lane & 3;
#pragma unroll
    for (int im = 0; im < 4; im++) {
#pragma unroll
        for (int jn = 0; jn < 8; jn++) {
            const int row = row0 + wm*64 + im*16 + g;
            const int col = col0 + wn*64 + jn*8 + tq*2;
            *(uint32_t*)(C + (size_t)row * Nc + col) =
                pack_h2(c[im][jn][0]*oscale, c[im][jn][1]*oscale);
            *(uint32_t*)(C + (size_t)(row + 8) * Nc + col) =
                pack_h2(c[im][jn][2]*oscale, c[im][jn][3]*oscale);
        }
    }
}

__global__ __launch_bounds__(128) void gemm_qkv()
{
    const int bx = blockIdx.x;
    const int row0 = blockIdx.y * 128;
    if (bx < 8)
        gemm_body128(g_xn, g_wTq,  g_q,  HDd,   row0, bx * 128, SOFT_SCALE);
    else
        gemm_body128(g_cn, g_wTkv, g_kv, 2*HDd, row0, (bx - 8) * 128, 1.0f);
}

// ============================================================
// O projection (measured-best R10 config): CTA 128x128,
// 4 warps (2x2), warp 64x64, 3-stage, grid (8, 32) = 256 CTAs.
// fp32 output via streaming stores (write-once, never re-read).
// ============================================================
__global__ __launch_bounds__(128) void gemm_o(float* __restrict__ out)
{
    extern __shared__ char gsm[];
    const uint32_t asb = smem_u32(gsm);
    const uint32_t bsb = asb + NSTAGE*CHUNKB;

    const int t = threadIdx.x;
    const int lane = t & 31, wid = t >> 5;
    const int wm = wid >> 1, wn = wid & 1;
    const int row0 = blockIdx.y * 128, col0 = blockIdx.x * 128;

    const int r0 = t >> 2, c8 = t & 3;
    const __half* Ap = g_ao  + (size_t)(row0 + r0) * KDIM + c8 * 8;
    const __half* Bp = g_wTo + (size_t)(col0 + r0) * KDIM + c8 * 8;
    const uint32_t st_off = (uint32_t)(r0 * 80 + c8 * 16);

    const uint32_t a_l_off = (uint32_t)((wm*64 + (lane & 7) + ((lane >> 3) & 1) * 8) * 80
                                        + ((lane >> 4) & 1) * 16);
    const uint32_t b_l_off = (uint32_t)((wn*64 + (lane & 7) + ((lane >> 4) & 1) * 8) * 80
                                        + ((lane >> 3) & 1) * 16);

    float c[4][8][4];
#pragma unroll
    for (int i = 0; i < 4; i++)
#pragma unroll
        for (int j = 0; j < 8; j++)
#pragma unroll
            for (int q = 0; q < 4; q++) c[i][j][q] = 0.f;

#pragma unroll
    for (int st = 0; st < 2; st++) {
#pragma unroll
        for (int i = 0; i < 4; i++) {
            CP16(asb + st*CHUNKB + st_off + i*(32*80), Ap + st*32 + (size_t)(32*i)*KDIM);
            CP16(bsb + st*CHUNKB + st_off + i*(32*80), Bp + st*32 + (size_t)(32*i)*KDIM);
        }
        CP_COMMIT();
    }

    for (int ch = 0; ch < 32; ch++) {
        CP_WAIT(1);
        __syncthreads();

        if (ch + 2 < 32) {
            const int st = (ch + 2) % 3;
#pragma unroll
            for (int i = 0; i < 4; i++) {
                CP16(asb + st*CHUNKB + st_off + i*(32*80), Ap + (ch+2)*32 + (size_t)(32*i)*KDIM);
                CP16(bsb + st*CHUNKB + st_off + i*(32*80), Bp + (ch+2)*32 + (size_t)(32*i)*KDIM);
            }
        }
        CP_COMMIT();

        const int cs = ch % 3;
        const uint32_t ab = asb + cs*CHUNKB + a_l_off;
        const uint32_t bb = bsb + cs*CHUNKB + b_l_off;
#pragma unroll
        for (int ks = 0; ks < 2; ks++) {
            uint32_t a[4][4], b[4][4];
#pragma unroll
            for (int im = 0; im < 4; im++)
                LDSM4(a[im], ab + im * (16*80) + ks * 32);
#pragma unroll
            for (int jq = 0; jq < 4; jq++)
                LDSM4(b[jq], bb + jq * (16*80) + ks * 32);
#pragma unroll
            for (int im = 0; im < 4; im++)
#pragma unroll
                for (int jq = 0; jq < 4; jq++) {
                    MMA16816(c[im][2*jq],   a[im], b[jq][0], b[jq][1]);
                    MMA16816(c[im][2*jq+1], a[im], b[jq][2], b[jq][3]);
                }
        }
    }

    const int g  = lane >> 2;
    const int tq = lane & 3;
#pragma unroll
    for (int im = 0; im < 4; im++) {
#pragma unroll
        for (int jn = 0; jn < 8; jn++) {
            const int row = row0 + wm*64 + im*16 + g;
            const int col = col0 + wn*64 + jn*8 + tq*2;
            STCS2(out + (size_t)row * Dd + col,       c[im][jn][0], c[im][jn][1]);
            STCS2(out + (size_t)(row + 8) * Dd + col, c[im][jn][2], c[im][jn][3]);
        }
    }
}

// ============================================================
// HMMA causal flash attention — R13 exact (measured best):
// 128 threads, 4 warps, 32 Q rows/warp (two 16-row blocks),
// BQ=128, BK=64, 3-buffer cp.async ring, longest-first,
// lsum via ones-column MMA, fp16 ex2, Q pre-scaled.
// ============================================================
#define BQ 128
#define BK 64
#define KPAD 72
#define KPADB 144
#define QS_H  (BQ*KPAD)
#define KVT_H (BK*KPAD)
#define FSM2 ((QS_H + 6*KVT_H) * 2)   // 73728

__global__ __launch_bounds__(128) void flash_hmma(
    const __half* __restrict__ q, const __half* __restrict__ kv,
    __half* __restrict__ o)
{
    extern __shared__ __half sh[];
    __half* Qs  = sh;
    __half* Vsp = sh + QS_H + 3*KVT_H;

    const int t = threadIdx.x, lane = t & 31, w = t >> 5;
    const int bq = gridDim.x - 1 - blockIdx.x;   // longest-first
    const int bh = blockIdx.y;
    const int b = bh >> 4, h = bh & 15;
    const int row0 = bq * BQ;

    const uint32_t shb = smem_u32(sh);
    const uint32_t ksb = shb + QS_H*2;
    const uint32_t vsb = ksb + 3*KVT_H*2;

#pragma unroll
    for (int i = 0; i < 8; i++) {
        int e = t + i * 128;
        int r = e >> 3, qq = e & 7;
        *(uint4*)(Qs + r * KPAD + qq * 8) =
            *(const uint4*)(q + (size_t)(b*Nn + row0 + r) * HDd + h * DHh + qq * 8);
    }
    for (int i = t; i < 192; i += 128) {
        const int buf = i >> 6, r = i & 63;
        uint4 ones = make_uint4(0x00003C00u, 0u, 0u, 0u);
        *(uint4*)(Vsp + buf * KVT_H + r * KPAD + 64) = ones;
    }

    const __half* kvbase = kv + (size_t)(b*Nn) * (2*HDd) + h * DHh;
    const int jt_max = row0 / BK + 1;

    const int lr = t >> 3, lq = t & 7;
    auto issue_kv = [&](int jt, int buf) {
        const uint32_t kd = ksb + (uint32_t)buf * (KVT_H*2);
        const uint32_t vd = vsb + (uint32_t)buf * (KVT_H*2);
#pragma unroll
        for (int rr = 0; rr < 64; rr += 16) {
            const __half* p = kvbase + (size_t)(jt*BK + lr + rr) * (2*HDd) + lq * 8;
            CP16(kd + (lr+rr)*KPADB + lq*16, p);
            CP16(vd + (lr+rr)*KPADB + lq*16, p + HDd);
        }
    };

    issue_kv(0, 0); CP_COMMIT();
    issue_kv(1, 1); CP_COMMIT();

    __syncthreads();

    uint32_t qf[2][4][4];
#pragma unroll
    for (int blk = 0; blk < 2; blk++) {
        const uint32_t qb = shb
            + (uint32_t)((w*32 + blk*16 + (lane & 7) + ((lane >> 3) & 1) * 8) * KPADB
                         + ((lane >> 4) & 1) * 16);
#pragma unroll
        for (int ks = 0; ks < 4; ks++)
            LDSM4(qf[blk][ks], qb + ks * 32);
    }

    const uint32_t k_off = (uint32_t)(((lane & 7) + ((lane >> 3) & 1) * 8) * KPADB
                                      + ((lane >> 4) & 1) * 16);
    const uint32_t v1_off = (uint32_t)(((lane & 7) + ((lane >> 3) & 1) * 8) * KPADB + 128);

    float m_prev[2][2] = {{-1e30f, -1e30f}, {-1e30f, -1e30f}};
    float oa[2][8][4];
    float oae[2][4];
#pragma unroll
    for (int blk = 0; blk < 2; blk++) {
#pragma unroll
        for (int jn = 0; jn < 8; jn++)
#pragma unroll
            for (int cc = 0; cc < 4; cc++) oa[blk][jn][cc] = 0.f;
#pragma unroll
        for (int cc = 0; cc < 4; cc++) oae[blk][cc] = 0.f;
    }

    const int wrow = row0 + w*32;
    const int lrow = wrow + (lane >> 2);

    for (int jt = 0; jt <= jt_max; jt++) {
        CP_WAIT(1);
        __syncthreads();

        if (jt + 2 <= jt_max) issue_kv(jt + 2, (jt + 2) % 3);
        CP_COMMIT();

        const bool full_masked = (jt*BK > wrow + 31);
        if (!full_masked) {
            const int buf = jt % 3;
            float sa[2][8][4];
#pragma unroll
            for (int blk = 0; blk < 2; blk++)
#pragma unroll
                for (int jn = 0; jn < 8; jn++)
#pragma unroll
                    for (int cc = 0; cc < 4; cc++) sa[blk][jn][cc] = 0.f;

            const uint32_t kb = ksb + (uint32_t)buf * (KVT_H*2) + k_off;
#pragma unroll
            for (int ks = 0; ks < 4; ks++) {
#pragma unroll
                for (int jp = 0; jp < 4; jp++) {
                    uint32_t kr[4];
                    LDSM4(kr, kb + jp * (16*KPADB) + ks * 32);
                    MMA16816(sa[0][2*jp],   qf[0][ks], kr[0], kr[2]);
                    MMA16816(sa[0][2*jp+1], qf[0][ks], kr[1], kr[3]);
                    MMA16816(sa[1][2*jp],   qf[1][ks], kr[0], kr[2]);
                    MMA16816(sa[1][2*jp+1], qf[1][ks], kr[1], kr[3]);
                }
            }

            const bool diag = (jt*BK + BK - 1 > wrow);
            if (diag) {
#pragma unroll
                for (int blk = 0; blk < 2; blk++)
#pragma unroll
                    for (int jn = 0; jn < 8; jn++)
#pragma unroll
                        for (int cc = 0; cc < 4; cc++) {
                            int col = jt*BK + jn*8 + (lane & 3)*2 + (cc & 1);
                            int row = lrow + blk*16 + (cc >> 1)*8;
                            if (col > row) sa[blk][jn][cc] = -1e30f;
                        }
            }

            float mnew[2][2], alpha[2][2];
#pragma unroll
            for (int blk = 0; blk < 2; blk++) {
                float rmax[2] = {-1e30f, -1e30f};
#pragma unroll
                for (int jn = 0; jn < 8; jn++) {
                    rmax[0] = fmaxf(rmax[0], fmaxf(sa[blk][jn][0], sa[blk][jn][1]));
                    rmax[1] = fmaxf(rmax[1], fmaxf(sa[blk][jn][2], sa[blk][jn][3]));
                }
#pragma unroll
                for (int k2 = 0; k2 < 2; k2++) {
                    rmax[k2] = fmaxf(rmax[k2], __shfl_xor_sync(0xffffffffu, rmax[k2], 1));
                    rmax[k2] = fmaxf(rmax[k2], __shfl_xor_sync(0xffffffffu, rmax[k2], 2));
                    mnew[blk][k2]  = fmaxf(m_prev[blk][k2], rmax[k2]);
                    alpha[blk][k2] = exp2f(m_prev[blk][k2] - mnew[blk][k2]);
                    m_prev[blk][k2] = mnew[blk][k2];
                }
            }
#pragma unroll
            for (int blk = 0; blk < 2; blk++) {
#pragma unroll
                for (int jn = 0; jn < 8; jn++)
#pragma unroll
                    for (int cc = 0; cc < 4; cc++)
                        oa[blk][jn][cc] *= alpha[blk][cc >> 1];
#pragma unroll
                for (int cc = 0; cc < 4; cc++)
                    oae[blk][cc] *= alpha[blk][cc >> 1];
            }

            uint32_t pf[2][4][4];
#pragma unroll
            for (int blk = 0; blk < 2; blk++)
#pragma unroll
                for (int ks = 0; ks < 4; ks++) {
                    uint32_t u0 = pack_h2(sa[blk][2*ks][0]   - mnew[blk][0], sa[blk][2*ks][1]   - mnew[blk][0]);
                    uint32_t u1 = pack_h2(sa[blk][2*ks][2]   - mnew[blk][1], sa[blk][2*ks][3]   - mnew[blk][1]);
                    uint32_t u2 = pack_h2(sa[blk][2*ks+1][0] - mnew[blk][0], sa[blk][2*ks+1][1] - mnew[blk][0]);
                    uint32_t u3 = pack_h2(sa[blk][2*ks+1][2] - mnew[blk][1], sa[blk][2*ks+1][3] - mnew[blk][1]);
                    HEX2(pf[blk][ks][0], u0);
                    HEX2(pf[blk][ks][1], u1);
                    HEX2(pf[blk][ks][2], u2);
                    HEX2(pf[blk][ks][3], u3);
                }

            const uint32_t vb  = vsb + (uint32_t)buf * (KVT_H*2) + k_off;
            const uint32_t vb1 = vsb + (uint32_t)buf * (KVT_H*2) + v1_off;
#pragma unroll
            for (int ks = 0; ks < 4; ks++) {
#pragma unroll
                for (int nb = 0; nb < 4; nb++) {
                    uint32_t vr[4];
                    LDSM4T(vr, vb + ks * (16*KPADB) + nb * 32);
                    MMA16816(oa[0][2*nb],   pf[0][ks], vr[0], vr[1]);
                    MMA16816(oa[0][2*nb+1], pf[0][ks], vr[2], vr[3]);
                    MMA16816(oa[1][2*nb],   pf[1][ks], vr[0], vr[1]);
                    MMA16816(oa[1][2*nb+1], pf[1][ks], vr[2], vr[3]);
                }
                uint32_t v1[2];
                LDSM2T(v1, vb1 + ks * (16*KPADB));
                MMA16816(oae[0], pf[0][ks], v1[0], v1[1]);
                MMA16816(oae[1], pf[1][ks], v1[0], v1[1]);
            }
        }
    }

#pragma unroll
    for (int blk = 0; blk < 2; blk++) {
        float l0 = __shfl_sync(0xffffffffu, oae[blk][0], lane & ~3);
        float l1 = __shfl_sync(0xffffffffu, oae[blk][2], lane & ~3);
        float inv0 = 1.f / l0, inv1 = 1.f / l1;
        __half* ob = o + (size_t)(b*Nn + lrow + blk*16) * HDd + h * DHh + (lane & 3) * 2;
#pragma unroll
        for (int jn = 0; jn < 8; jn++) {
            *(uint32_t*)(ob + jn*8)         = pack_h2(oa[blk][jn][0]*inv0, oa[blk][jn][1]*inv0);
            *(uint32_t*)(ob + 8*HDd + jn*8) = pack_h2(oa[blk][jn][2]*inv1, oa[blk][jn][3]*inv1);
        }
    }
}

// ============================================================
// launch
// ============================================================
extern "C" void kernel_launch(void* const* d_in, const int* in_sizes, int n_in,
                              void* d_out, int out_size)
{
    const float* x     = (const float*)d_in[0];
    const float* ln_g  = (const float*)d_in[1];
    const float* ln_b  = (const float*)d_in[2];
    const float* lnc_g = (const float*)d_in[3];
    const float* lnc_b = (const float*)d_in[4];
    const float* Wq    = (const float*)d_in[5];
    const float* Wkv   = (const float*)d_in[6];
    const float* Wo    = (const float*)d_in[7];
    float* out = (float*)d_out;

    __half *qp, *kvp, *aop;
    cudaGetSymbolAddress((void**)&qp,  g_q);
    cudaGetSymbolAddress((void**)&kvp, g_kv);
    cudaGetSymbolAddress((void**)&aop, g_ao);

    cudaFuncSetAttribute(flash_hmma,
                         cudaFuncAttributeMaxDynamicSharedMemorySize, FSM2);
    cudaFuncSetAttribute(gemm_qkv,
                         cudaFuncAttributeMaxDynamicSharedMemorySize, GSMEM);
    cudaFuncSetAttribute(gemm_o,
                         cudaFuncAttributeMaxDynamicSharedMemorySize, GSMEM);

    // 1) merged layernorm (vectorized) + weight transposes
    prep_kernel<<<Mm + 4096, 256>>>(x, ln_g, ln_b, lnc_g, lnc_b, Wq, Wkv, Wo);
    // 2) fused q (pre-scaled) + kv projections
    gemm_qkv<<<dim3(24, Mm/128), 128, GSMEM>>>();
    // 3) HMMA causal flash attention (R13 exact)
    flash_hmma<<<dim3(Nn/BQ, Bb*Hh), 128, FSM2>>>(qp, kvp, aop);
    // 4) out = ao @ Wo (128x128 tiles, streaming stores)
    gemm_o<<<dim3(Dd/128, Mm/128), 128, GSMEM>>>(out);
}